// round 1
// baseline (speedup 1.0000x reference)
#include <cuda_runtime.h>

#define BB 2
#define NN 40000
#define EE 400000
#define RR 64
#define DD 64
#define LLAYERS 6

// Scratch (allocation-free rule: __device__ globals)
__device__ __align__(16) float g_x[BB * NN * DD];      // 20.5 MB
__device__ __align__(16) float g_agg[BB * NN * DD];    // 20.5 MB
__device__ __align__(16) float g_rel[BB * RR * DD];
__device__ __align__(16) float g_query[BB * DD];
__device__ __align__(16) float g_qpart[BB * 2 * DD];

// ---------------------------------------------------------------------------
// prep: query[b] = rel_reps[b, r_index[b]];
//       qpart[b][e] = sum_k query[k]*mlp_w[64+k][e] + mlp_b[e]
// ---------------------------------------------------------------------------
__global__ void prep_kernel(const float* __restrict__ rel_reps,
                            const int* __restrict__ r_index,
                            const float* __restrict__ mlp_w,
                            const float* __restrict__ mlp_b) {
    __shared__ float q_s[BB * DD];
    int t = threadIdx.x;  // 256
    if (t < BB * DD) {
        int b = t / DD, d = t % DD;
        float v = rel_reps[(b * RR + r_index[b]) * DD + d];
        g_query[t] = v;
        q_s[t] = v;
    }
    __syncthreads();
    int b = t / 128, e = t % 128;
    float acc = mlp_b[e];
#pragma unroll
    for (int k = 0; k < DD; k++)
        acc = fmaf(q_s[b * DD + k], mlp_w[(DD + k) * 128 + e], acc);
    g_qpart[b * 128 + e] = acc;
}

// ---------------------------------------------------------------------------
// init x or agg with boundary: zeros everywhere, query at h_index[b]
// which = 0 -> g_x, which = 1 -> g_agg
// ---------------------------------------------------------------------------
__global__ void init_state(int which, const int* __restrict__ h_index) {
    int gid = blockIdx.x * 256 + threadIdx.x;
    const int per_b = NN * DD / 4;  // 640000 float4
    if (gid >= BB * per_b) return;
    int b = gid / per_b;
    int r = gid - b * per_b;
    int n = r >> 4;
    int d4 = r & 15;
    float4 v = make_float4(0.f, 0.f, 0.f, 0.f);
    if (n == __ldg(&h_index[b]))
        v = *(const float4*)&g_query[b * DD + d4 * 4];
    float4* dst = which ? (float4*)g_agg : (float4*)g_x;
    dst[gid] = v;
}

// ---------------------------------------------------------------------------
// per-layer relation projection: rel = relu(rel_reps@W1+b1)@W2+b2
// block = one (b,r) pair, 64 threads (thread = output dim)
// ---------------------------------------------------------------------------
__global__ void relproj_kernel(const float* __restrict__ rel_reps,
                               const float* __restrict__ pw1,
                               const float* __restrict__ pb1,
                               const float* __restrict__ pw2,
                               const float* __restrict__ pb2, int l) {
    int br = blockIdx.x;  // b*RR + r
    int e = threadIdx.x;  // 64
    __shared__ float in_s[DD];
    __shared__ float hid_s[DD];
    in_s[e] = rel_reps[br * DD + e];
    __syncthreads();
    const float* W1 = pw1 + l * DD * DD;
    float acc = pb1[l * DD + e];
#pragma unroll 16
    for (int k = 0; k < DD; k++) acc = fmaf(in_s[k], W1[k * DD + e], acc);
    hid_s[e] = fmaxf(acc, 0.f);
    __syncthreads();
    const float* W2 = pw2 + l * DD * DD;
    float acc2 = pb2[l * DD + e];
#pragma unroll 16
    for (int k = 0; k < DD; k++) acc2 = fmaf(hid_s[k], W2[k * DD + e], acc2);
    g_rel[br * DD + e] = acc2;
}

// ---------------------------------------------------------------------------
// distmult message + scatter-sum: agg[b,dst] += x[b,src] * rel[b,type]
// 16 "lanes" (float4 chunks) per edge. rel in smem (both batches, 32KB).
// Zero x-rows are skipped (exact: contribute 0 to the sum).
// ---------------------------------------------------------------------------
__global__ void message_kernel(const int* __restrict__ edge_index,
                               const int* __restrict__ edge_type) {
    __shared__ float rel_s[BB * RR * DD];
    for (int i = threadIdx.x; i < BB * RR * DD; i += blockDim.x)
        rel_s[i] = g_rel[i];
    __syncthreads();
    const int total = BB * EE * 16;
    const int stride = gridDim.x * blockDim.x;
    for (int gid = blockIdx.x * blockDim.x + threadIdx.x; gid < total;
         gid += stride) {
        int c = gid & 15;
        int et = gid >> 4;
        int b = (et >= EE) ? 1 : 0;
        int e = et - b * EE;
        int src = __ldg(&edge_index[e]);
        const float4 xv = *(const float4*)&g_x[(b * NN + src) * DD + c * 4];
        if (xv.x == 0.f && xv.y == 0.f && xv.z == 0.f && xv.w == 0.f) continue;
        int dst = __ldg(&edge_index[EE + e]);
        int ty = __ldg(&edge_type[e]);
        const float4 rv = *(const float4*)&rel_s[(b * RR + ty) * DD + c * 4];
        float mx = xv.x * rv.x, my = xv.y * rv.y, mz = xv.z * rv.z,
              mw = xv.w * rv.w;
        float* p = &g_agg[(b * NN + dst) * DD + c * 4];
        asm volatile("red.global.add.v4.f32 [%0], {%1,%2,%3,%4};" ::"l"(p),
                     "f"(mx), "f"(my), "f"(mz), "f"(mw)
                     : "memory");
    }
}

// ---------------------------------------------------------------------------
// fused: out = relu(LN(cat(x,agg)@W + b)) + x   (written back into g_x)
// block = 64 nodes, 256 threads, 4x4 register tile per thread.
// LN reduced via half-warp (16-lane) shuffles — D=64 dims live across the
// 16 td-groups (4 each).
// ---------------------------------------------------------------------------
__global__ void linear_kernel(const float* __restrict__ lin_w,
                              const float* __restrict__ lin_b,
                              const float* __restrict__ ln_g,
                              const float* __restrict__ ln_b, int l) {
    extern __shared__ float smem[];
    float* W_s = smem;              // [128][64] = 32KB
    float* cat_s = smem + 128 * 64; // [k][node] transposed = 32KB
    int b = blockIdx.y;
    int n0 = blockIdx.x * 64;
    int t = threadIdx.x;  // 256

    // load weights (8192 floats)
    const float4* Wg = (const float4*)(lin_w + l * 128 * 64);
    float4* Ws4 = (float4*)W_s;
#pragma unroll
    for (int i = 0; i < 8; i++) Ws4[t + i * 256] = Wg[t + i * 256];

    // load cat = [x ; agg] transposed into smem
    const float* xb = g_x + (b * NN + n0) * DD;
    const float* ab = g_agg + (b * NN + n0) * DD;
    int nl = t & 63;
    int c0 = t >> 6;  // 0..3
#pragma unroll
    for (int i = 0; i < 4; i++) {
        int cc = c0 + i * 4;  // float4 col 0..15
        float4 v = *(const float4*)&xb[nl * DD + cc * 4];
        cat_s[(cc * 4 + 0) * 64 + nl] = v.x;
        cat_s[(cc * 4 + 1) * 64 + nl] = v.y;
        cat_s[(cc * 4 + 2) * 64 + nl] = v.z;
        cat_s[(cc * 4 + 3) * 64 + nl] = v.w;
        float4 a = *(const float4*)&ab[nl * DD + cc * 4];
        cat_s[(64 + cc * 4 + 0) * 64 + nl] = a.x;
        cat_s[(64 + cc * 4 + 1) * 64 + nl] = a.y;
        cat_s[(64 + cc * 4 + 2) * 64 + nl] = a.z;
        cat_s[(64 + cc * 4 + 3) * 64 + nl] = a.w;
    }
    __syncthreads();

    int tn = t >> 4;  // node group (4 nodes)
    int td = t & 15;  // dim group  (4 dims)
    float4 bias4 = *(const float4*)&lin_b[l * 64 + td * 4];
    float acc[4][4];
#pragma unroll
    for (int i = 0; i < 4; i++) {
        acc[i][0] = bias4.x; acc[i][1] = bias4.y;
        acc[i][2] = bias4.z; acc[i][3] = bias4.w;
    }

#pragma unroll 4
    for (int k = 0; k < 128; ++k) {
        const float4 a4 = *(const float4*)(cat_s + k * 64 + tn * 4);
        const float4 w4 = *(const float4*)(W_s + k * 64 + td * 4);
        float aa[4] = {a4.x, a4.y, a4.z, a4.w};
        float ww[4] = {w4.x, w4.y, w4.z, w4.w};
#pragma unroll
        for (int i = 0; i < 4; i++)
#pragma unroll
            for (int j = 0; j < 4; j++)
                acc[i][j] = fmaf(aa[i], ww[j], acc[i][j]);
    }

    // fused LayerNorm + relu + shortcut, write back to g_x
    float4 g4 = *(const float4*)&ln_g[l * 64 + td * 4];
    float4 bb4 = *(const float4*)&ln_b[l * 64 + td * 4];
    float lng[4] = {g4.x, g4.y, g4.z, g4.w};
    float lnb[4] = {bb4.x, bb4.y, bb4.z, bb4.w};
    float* xrow = g_x + (b * NN + n0) * DD;
#pragma unroll
    for (int i = 0; i < 4; i++) {
        float s = acc[i][0] + acc[i][1] + acc[i][2] + acc[i][3];
        float s2 = acc[i][0] * acc[i][0] + acc[i][1] * acc[i][1] +
                   acc[i][2] * acc[i][2] + acc[i][3] * acc[i][3];
#pragma unroll
        for (int m = 1; m < 16; m <<= 1) {
            s += __shfl_xor_sync(0xffffffffu, s, m);
            s2 += __shfl_xor_sync(0xffffffffu, s2, m);
        }
        float mu = s * (1.f / 64.f);
        float var = s2 * (1.f / 64.f) - mu * mu;
        float inv = rsqrtf(var + 1e-5f);
        int n = tn * 4 + i;
        float4 xold = *(const float4*)&xrow[n * DD + td * 4];
        float4 o;
        o.x = fmaxf((acc[i][0] - mu) * inv * lng[0] + lnb[0], 0.f) + xold.x;
        o.y = fmaxf((acc[i][1] - mu) * inv * lng[1] + lnb[1], 0.f) + xold.y;
        o.z = fmaxf((acc[i][2] - mu) * inv * lng[2] + lnb[2], 0.f) + xold.z;
        o.w = fmaxf((acc[i][3] - mu) * inv * lng[3] + lnb[3], 0.f) + xold.w;
        *(float4*)&xrow[n * DD + td * 4] = o;
    }
}

// ---------------------------------------------------------------------------
// final: out = relu([x ; query] @ mlp_w + mlp_b)
// query part precomputed into g_qpart, so K=64 GEMM only.
// block = 64 nodes, 256 threads, 4 nodes x 8 dims per thread.
// ---------------------------------------------------------------------------
__global__ void final_kernel(const float* __restrict__ mlp_w,
                             float* __restrict__ out) {
    extern __shared__ float smem[];
    float* W_s = smem;             // [64][128] first 64 rows = 32KB
    float* x_s = smem + 64 * 128;  // [k][node] = 16KB
    int b = blockIdx.y;
    int n0 = blockIdx.x * 64;
    int t = threadIdx.x;

    const float4* Wg = (const float4*)mlp_w;  // first 64 rows = 2048 float4
    float4* Ws4 = (float4*)W_s;
#pragma unroll
    for (int i = 0; i < 8; i++) Ws4[t + i * 256] = Wg[t + i * 256];

    const float* xb = g_x + (b * NN + n0) * DD;
    int nl = t & 63;
    int c0 = t >> 6;
#pragma unroll
    for (int i = 0; i < 4; i++) {
        int cc = c0 + i * 4;
        float4 v = *(const float4*)&xb[nl * DD + cc * 4];
        x_s[(cc * 4 + 0) * 64 + nl] = v.x;
        x_s[(cc * 4 + 1) * 64 + nl] = v.y;
        x_s[(cc * 4 + 2) * 64 + nl] = v.z;
        x_s[(cc * 4 + 3) * 64 + nl] = v.w;
    }
    __syncthreads();

    int tn = t >> 4;  // 16 node groups (4 nodes each)
    int td = t & 15;  // 16 dim groups (8 dims each)
    float acc[4][8];
#pragma unroll
    for (int i = 0; i < 4; i++)
#pragma unroll
        for (int j = 0; j < 8; j++) acc[i][j] = 0.f;

#pragma unroll 4
    for (int k = 0; k < 64; ++k) {
        const float4 a4 = *(const float4*)(x_s + k * 64 + tn * 4);
        const float4 w0 = *(const float4*)(W_s + k * 128 + td * 8);
        const float4 w1 = *(const float4*)(W_s + k * 128 + td * 8 + 4);
        float aa[4] = {a4.x, a4.y, a4.z, a4.w};
        float ww[8] = {w0.x, w0.y, w0.z, w0.w, w1.x, w1.y, w1.z, w1.w};
#pragma unroll
        for (int i = 0; i < 4; i++)
#pragma unroll
            for (int j = 0; j < 8; j++)
                acc[i][j] = fmaf(aa[i], ww[j], acc[i][j]);
    }

    float qp[8];
    const float4 q0 = *(const float4*)&g_qpart[b * 128 + td * 8];
    const float4 q1 = *(const float4*)&g_qpart[b * 128 + td * 8 + 4];
    qp[0] = q0.x; qp[1] = q0.y; qp[2] = q0.z; qp[3] = q0.w;
    qp[4] = q1.x; qp[5] = q1.y; qp[6] = q1.z; qp[7] = q1.w;

#pragma unroll
    for (int i = 0; i < 4; i++) {
        int n = n0 + tn * 4 + i;
        float* op = out + ((long)(b * NN + n)) * 128 + td * 8;
        float4 o0, o1;
        o0.x = fmaxf(acc[i][0] + qp[0], 0.f);
        o0.y = fmaxf(acc[i][1] + qp[1], 0.f);
        o0.z = fmaxf(acc[i][2] + qp[2], 0.f);
        o0.w = fmaxf(acc[i][3] + qp[3], 0.f);
        o1.x = fmaxf(acc[i][4] + qp[4], 0.f);
        o1.y = fmaxf(acc[i][5] + qp[5], 0.f);
        o1.z = fmaxf(acc[i][6] + qp[6], 0.f);
        o1.w = fmaxf(acc[i][7] + qp[7], 0.f);
        *(float4*)op = o0;
        *(float4*)(op + 4) = o1;
    }
}

// ---------------------------------------------------------------------------
extern "C" void kernel_launch(void* const* d_in, const int* in_sizes, int n_in,
                              void* d_out, int out_size) {
    const float* rel_reps = (const float*)d_in[0];
    const int* h_index = (const int*)d_in[1];
    const int* r_index = (const int*)d_in[2];
    const int* edge_index = (const int*)d_in[3];
    const int* edge_type = (const int*)d_in[4];
    const float* pw1 = (const float*)d_in[5];
    const float* pb1 = (const float*)d_in[6];
    const float* pw2 = (const float*)d_in[7];
    const float* pb2 = (const float*)d_in[8];
    const float* lin_w = (const float*)d_in[9];
    const float* lin_b = (const float*)d_in[10];
    const float* ln_g = (const float*)d_in[11];
    const float* ln_b = (const float*)d_in[12];
    const float* mlp_w = (const float*)d_in[13];
    const float* mlp_b = (const float*)d_in[14];
    float* out = (float*)d_out;

    cudaFuncSetAttribute(linear_kernel,
                         cudaFuncAttributeMaxDynamicSharedMemorySize, 65536);
    cudaFuncSetAttribute(final_kernel,
                         cudaFuncAttributeMaxDynamicSharedMemorySize, 49152);

    const int init_blocks = (BB * NN * DD / 4 + 255) / 256;

    prep_kernel<<<1, 256>>>(rel_reps, r_index, mlp_w, mlp_b);
    init_state<<<init_blocks, 256>>>(0, h_index);
    for (int l = 0; l < LLAYERS; l++) {
        relproj_kernel<<<BB * RR, 64>>>(rel_reps, pw1, pb1, pw2, pb2, l);
        init_state<<<init_blocks, 256>>>(1, h_index);
        message_kernel<<<1776, 256>>>(edge_index, edge_type);
        linear_kernel<<<dim3(NN / 64, BB), 256, 65536>>>(lin_w, lin_b, ln_g,
                                                         ln_b, l);
    }
    final_kernel<<<dim3(NN / 64, BB), 256, 49152>>>(mlp_w, out);
}